// round 15
// baseline (speedup 1.0000x reference)
#include <cuda_runtime.h>
#include <cstdint>

#define WIDTH  1024
#define HALF   512
#define DEPTH  8
#define BDEPTH 10
#define BATCH  65536

typedef unsigned long long ull;

// Geometry (champion):
//   lane = p bits [6:2]  (32 lanes)
//   slot v (0..31): p = ((v>>2)<<7) | (lane<<2) | (v&3)   -> v bits = p bits {1,0,9,8,7}
//   thread holds val[v*2+h]: h=0 rows(0,1), h=1 rows(2,3) packed in f32x2.
// Steps t (bit b = 9-t): t=0,1,2 reg (v bits 4,3,2); t=3..7 lane (lane bits 4..0);
//                        t=8,9 reg (v bits 1,0).
//
// g_bt (steps t=1..9): 256 float4 per step, LDG.128:
//   reg step:  entry[e*32 + lane], e=0..7:  (c[pi=2e], s[2e], c[2e+1], s[2e+1])
//   lane step: entry[e*16 + lp],  e=0..15: (c[v=2e],  s[2e], c[2e+1], s[2e+1])
// g_t0 (step t=0, scale-folded): entry[L*512 + pi*32 + lane] = (a, b, -g, d)
//   n0 = a*x0 + b*x1 ; n1 = (-g)*x0 + d*x1 with a=c*sc0, b=s*sc1, g=s*sc0, d=c*sc1
//   (sc = previous layer's quintic scale; sc=1 for layer 0).
__device__ float4 g_bt[DEPTH * BDEPTH * 256];
__device__ float4 g_t0[DEPTH * 512];
// quintic (scale folded out): entry[act*512 + e*32 + lane] = (m_v0, nb_v0, m_v1, nb_v1)
__device__ float4 g_qt[(DEPTH - 1) * 512];

// ---------- f32x2 helpers ----------
__device__ __forceinline__ ull pk(float lo, float hi) {
    ull r;
    asm("mov.b64 %0, {%1, %2};" : "=l"(r) : "r"(__float_as_uint(lo)), "r"(__float_as_uint(hi)));
    return r;
}
__device__ __forceinline__ void unpk(ull v, float& lo, float& hi) {
    unsigned a, b;
    asm("mov.b64 {%0, %1}, %2;" : "=r"(a), "=r"(b) : "l"(v));
    lo = __uint_as_float(a);
    hi = __uint_as_float(b);
}
__device__ __forceinline__ ull f2mul(ull a, ull b) {
    ull r;
    asm("mul.rn.f32x2 %0, %1, %2;" : "=l"(r) : "l"(a), "l"(b));
    return r;
}
__device__ __forceinline__ ull f2fma(ull a, ull b, ull c) {
    ull r;
    asm("fma.rn.f32x2 %0, %1, %2, %3;" : "=l"(r) : "l"(a), "l"(b), "l"(c));
    return r;
}
__device__ __forceinline__ void cfence() { asm volatile("" ::: "memory"); }

// ---------- prep ----------
#define BT_ELEMS (DEPTH * BDEPTH * 256)
#define T0_ELEMS (DEPTH * 512)
#define QT_ELEMS ((DEPTH - 1) * 512)

__device__ __forceinline__ float theta_of(const float* bp, int layer, int t, int p0) {
    int j = 0;
#pragma unroll
    for (int k = 0; k < 9; k++) {
        int src = ((k - t) % 10 + 10) % 10;
        j |= ((p0 >> src) & 1) << k;
    }
    return bp[layer * (HALF * BDEPTH) + j * BDEPTH + t];
}

__global__ void prep_all(const float* __restrict__ bp,
                         const float* __restrict__ bias,
                         const float* __restrict__ slope,
                         const float* __restrict__ scale) {
    int e0 = blockIdx.x * blockDim.x + threadIdx.x;
    if (e0 < BT_ELEMS) {
        int T = e0 >> 8;
        int idx = e0 & 255;
        int layer = T / BDEPTH;
        int t = T % BDEPTH;
        if (t == 0) return;  // t=0 handled via g_t0
        int b = 9 - t;

        float4 out;
        if (b >= 7 || b <= 1) {
            int sbit = (b >= 7) ? (b - 5) : b;
            int m = 1 << sbit;
            int e = idx >> 5;
            int lane = idx & 31;
            float cs[4];
#pragma unroll
            for (int k = 0; k < 2; k++) {
                int pi = 2 * e + k;
                int v0 = (pi & (m - 1)) | ((pi & ~(m - 1)) << 1);
                int p0 = ((v0 >> 2) << 7) | (lane << 2) | (v0 & 3);
                float th = theta_of(bp, layer, t, p0);
                float s, c;
                sincosf(th, &s, &c);
                cs[2 * k] = c;
                cs[2 * k + 1] = s;
            }
            out = make_float4(cs[0], cs[1], cs[2], cs[3]);
        } else {
            int lm = 1 << (b - 2);
            int e = idx >> 4;
            int lp = idx & 15;
            int l0 = (lp & (lm - 1)) | ((lp & ~(lm - 1)) << 1);
            float cs[4];
#pragma unroll
            for (int k = 0; k < 2; k++) {
                int v = 2 * e + k;
                int p0 = ((v >> 2) << 7) | (l0 << 2) | (v & 3);
                float th = theta_of(bp, layer, t, p0);
                float s, c;
                sincosf(th, &s, &c);
                cs[2 * k] = c;
                cs[2 * k + 1] = s;
            }
            out = make_float4(cs[0], cs[1], cs[2], cs[3]);
        }
        g_bt[e0] = out;
    } else if (e0 < BT_ELEMS + T0_ELEMS) {
        int q = e0 - BT_ELEMS;
        int layer = q >> 9;
        int idx = q & 511;
        int pi = idx >> 5;          // pair 0..15: v0 = pi, v1 = pi|16 (M=16)
        int lane = idx & 31;
        int v0 = pi, v1 = pi | 16;
        int p0 = ((v0 >> 2) << 7) | (lane << 2) | (v0 & 3);
        int p1 = ((v1 >> 2) << 7) | (lane << 2) | (v1 & 3);
        float th = theta_of(bp, layer, 0, p0);
        float s, c;
        sincosf(th, &s, &c);
        float sc0 = 1.0f, sc1 = 1.0f;
        if (layer > 0) {
            sc0 = scale[(layer - 1) * WIDTH + p0];
            sc1 = scale[(layer - 1) * WIDTH + p1];
        }
        g_t0[q] = make_float4(c * sc0, s * sc1, -s * sc0, c * sc1);
    } else if (e0 < BT_ELEMS + T0_ELEMS + QT_ELEMS) {
        int q = e0 - BT_ELEMS - T0_ELEMS;
        int act = q >> 9;
        int idx = q & 511;
        int e = idx >> 5;           // v0 = 2e, v1 = 2e+1
        int l = idx & 31;
        float mv[2], nbv[2];
#pragma unroll
        for (int k = 0; k < 2; k++) {
            int v = 2 * e + k;
            int p0 = ((v >> 2) << 7) | (l << 2) | (v & 3);
            float bi = bias[act * WIDTH + p0];
            float sl = slope[act * WIDTH + p0];
            float sc = scale[act * WIDTH + p0];
            mv[k] = sl / sc;
            nbv[k] = -bi / sc;
        }
        g_qt[q] = make_float4(mv[0], nbv[0], mv[1], nbv[1]);
    }
}

// ---------- main kernel ----------

__device__ __forceinline__ void bfly_pair(ull (&val)[64], int v0, int v1, float c, float s) {
    ull c2 = pk(c, c);
    ull s2 = pk(s, s);
    ull ns2 = s2 ^ 0x8000000080000000ULL;
#pragma unroll
    for (int h = 0; h < 2; h++) {
        ull x0 = val[v0 * 2 + h];
        ull x1 = val[v1 * 2 + h];
        val[v0 * 2 + h] = f2fma(c2, x0, f2mul(s2, x1));   // n0 =  c*x0 + s*x1
        val[v1 * 2 + h] = f2fma(c2, x1, f2mul(ns2, x0));  // n1 =  c*x1 - s*x0
    }
}

// t=0 with folded scale: n0 = a*x0 + b*x1 ; n1 = g*x0 + d*x1 (g pre-negated)
__device__ __forceinline__ void t0_step(ull (&val)[64], int lane, const float4* __restrict__ t0t) {
#pragma unroll
    for (int pi = 0; pi < 16; pi++) {
        float4 q = __ldg(t0t + pi * 32 + lane);
        ull a2 = pk(q.x, q.x);
        ull b2 = pk(q.y, q.y);
        ull g2 = pk(q.z, q.z);
        ull d2 = pk(q.w, q.w);
        const int v0 = pi, v1 = pi | 16;
#pragma unroll
        for (int h = 0; h < 2; h++) {
            ull x0 = val[v0 * 2 + h];
            ull x1 = val[v1 * 2 + h];
            val[v0 * 2 + h] = f2fma(a2, x0, f2mul(b2, x1));
            val[v1 * 2 + h] = f2fma(g2, x0, f2mul(d2, x1));
        }
        if ((pi & 3) == 3) cfence();
    }
}

template <int M>
__device__ __forceinline__ void reg_step(ull (&val)[64], int lane, const float4* __restrict__ bt) {
#pragma unroll
    for (int e = 0; e < 8; e++) {
        float4 q = __ldg(bt + e * 32 + lane);
        {
            const int pi = 2 * e;
            const int v0 = (pi & (M - 1)) | ((pi & ~(M - 1)) << 1);
            bfly_pair(val, v0, v0 | M, q.x, q.y);
        }
        {
            const int pi = 2 * e + 1;
            const int v0 = (pi & (M - 1)) | ((pi & ~(M - 1)) << 1);
            bfly_pair(val, v0, v0 | M, q.z, q.w);
        }
        if ((e & 3) == 3) cfence();
    }
}

// Lane butterfly: all 4 partner shuffles per table fetch issued up front.
template <int LM>
__device__ __forceinline__ void lane_step(ull (&val)[64], int lane, const float4* __restrict__ bt) {
    const ull smask = (lane & LM) ? 0x8000000080000000ULL : 0ULL;
    const int lp = (lane & (LM - 1)) | ((lane >> 1) & ~(LM - 1));
#pragma unroll
    for (int e = 0; e < 16; e++) {
        float4 q = __ldg(bt + e * 16 + lp);
        const int va = 2 * e;
        const int vb = 2 * e + 1;
        ull xa0 = val[va * 2 + 0];
        ull xa1 = val[va * 2 + 1];
        ull xb0 = val[vb * 2 + 0];
        ull xb1 = val[vb * 2 + 1];
        ull pa0 = __shfl_xor_sync(0xffffffffu, xa0, LM);
        ull pa1 = __shfl_xor_sync(0xffffffffu, xa1, LM);
        ull pb0 = __shfl_xor_sync(0xffffffffu, xb0, LM);
        ull pb1 = __shfl_xor_sync(0xffffffffu, xb1, LM);
        ull ca = pk(q.x, q.x);
        ull sa = pk(q.y, q.y) ^ smask;
        ull cb = pk(q.z, q.z);
        ull sb = pk(q.w, q.w) ^ smask;
        val[va * 2 + 0] = f2fma(ca, xa0, f2mul(sa, pa0));
        val[va * 2 + 1] = f2fma(ca, xa1, f2mul(sa, pa1));
        val[vb * 2 + 0] = f2fma(cb, xb0, f2mul(sb, pb0));
        val[vb * 2 + 1] = f2fma(cb, xb1, f2mul(sb, pb1));
        if ((e & 3) == 3) cfence();
    }
}

// quintic WITHOUT trailing scale (folded into next layer's t0)
__device__ __forceinline__ void quintic(ull (&val)[64], int lane, int act) {
    const float4* __restrict__ qt = g_qt + act * 512;
    const ull C1875 = 0x3FF000003FF00000ULL;  // (1.875, 1.875)
    const ull CM125 = 0xBFA00000BFA00000ULL;  // (-1.25, -1.25)
    const ull C0375 = 0x3EC000003EC00000ULL;  // (0.375, 0.375)
#pragma unroll
    for (int e = 0; e < 16; e++) {
        float4 q = __ldg(qt + e * 32 + lane);
#pragma unroll
        for (int k = 0; k < 2; k++) {
            const int v = 2 * e + k;
            ull m2 = pk(k ? q.z : q.x, k ? q.z : q.x);
            ull nb2 = pk(k ? q.w : q.y, k ? q.w : q.y);
#pragma unroll
            for (int h = 0; h < 2; h++) {
                ull u = f2fma(val[v * 2 + h], m2, nb2);
                float lo, hi;
                unpk(u, lo, hi);
                lo = fminf(fmaxf(lo, -1.0f), 1.0f);
                hi = fminf(fmaxf(hi, -1.0f), 1.0f);
                u = pk(lo, hi);
                ull u2 = f2mul(u, u);
                ull p = f2fma(u2, C0375, CM125);
                p = f2fma(u2, p, C1875);
                val[v * 2 + h] = f2mul(u, p);
            }
        }
        if ((e & 3) == 3) cfence();
    }
}

// 96-thread CTAs, 3 CTAs/SM -> 9 warps/SM at a 227-reg budget: fills the
// latency bubbles (L1 busy 72.6%, issue 44%) without cutting into the ~170-reg
// live set (R7/R9 proved 168 spills; 227 only trims prefetch slack).
__global__ void __launch_bounds__(96, 3)
net_kernel(const float* __restrict__ X, float* __restrict__ Y) {
    const int lane = threadIdx.x & 31;
    const int w = blockIdx.x * 3 + (threadIdx.x >> 5);
    if (w >= BATCH / 4) return;
    const long long row0 = (long long)w * 4;
    const float* __restrict__ xr0 = X + row0 * WIDTH;
    const float* __restrict__ xr1 = xr0 + WIDTH;
    const float* __restrict__ xr2 = xr1 + WIDTH;
    const float* __restrict__ xr3 = xr2 + WIDTH;

    ull val[64];

    // load: 4 rows; val[v*2+h]: h=0 -> (row0,row1), h=1 -> (row2,row3)
#pragma unroll
    for (int vhi = 0; vhi < 8; vhi++) {
        int off = vhi * 128 + lane * 4;
        int s = vhi * 4;
        {
            float4 a = *(const float4*)(xr0 + off);
            float4 b = *(const float4*)(xr1 + off);
            val[(s + 0) * 2 + 0] = pk(a.x, b.x);
            val[(s + 1) * 2 + 0] = pk(a.y, b.y);
            val[(s + 2) * 2 + 0] = pk(a.z, b.z);
            val[(s + 3) * 2 + 0] = pk(a.w, b.w);
        }
        cfence();
        {
            float4 c = *(const float4*)(xr2 + off);
            float4 d = *(const float4*)(xr3 + off);
            val[(s + 0) * 2 + 1] = pk(c.x, d.x);
            val[(s + 1) * 2 + 1] = pk(c.y, d.y);
            val[(s + 2) * 2 + 1] = pk(c.z, d.z);
            val[(s + 3) * 2 + 1] = pk(c.w, d.w);
        }
        cfence();
    }

#pragma unroll 1
    for (int layer = 0; layer < DEPTH; layer++) {
        const float4* __restrict__ bt = g_bt + layer * (BDEPTH * 256);
        t0_step(val, lane, g_t0 + layer * 512);  // t=0: p bit 9, scale-folded
        reg_step<8>(val, lane, bt + 1 * 256);    // t=1: p bit 8 (v bit 3)
        reg_step<4>(val, lane, bt + 2 * 256);    // t=2: p bit 7 (v bit 2)
        lane_step<16>(val, lane, bt + 3 * 256);  // t=3: p bit 6 (lane bit 4)
        lane_step<8>(val, lane, bt + 4 * 256);   // t=4: p bit 5
        lane_step<4>(val, lane, bt + 5 * 256);   // t=5: p bit 4
        lane_step<2>(val, lane, bt + 6 * 256);   // t=6: p bit 3
        lane_step<1>(val, lane, bt + 7 * 256);   // t=7: p bit 2 (lane bit 0)
        reg_step<2>(val, lane, bt + 8 * 256);    // t=8: p bit 1 (v bit 1)
        reg_step<1>(val, lane, bt + 9 * 256);    // t=9: p bit 0 (v bit 0)
        if (layer < DEPTH - 1) quintic(val, lane, layer);
    }

    // store (net permutation over 10 steps per layer is identity)
    float* __restrict__ yr0 = Y + row0 * WIDTH;
    float* __restrict__ yr1 = yr0 + WIDTH;
    float* __restrict__ yr2 = yr1 + WIDTH;
    float* __restrict__ yr3 = yr2 + WIDTH;
#pragma unroll
    for (int vhi = 0; vhi < 8; vhi++) {
        int off = vhi * 128 + lane * 4;
        int s = vhi * 4;
        {
            float4 a, b;
            unpk(val[(s + 0) * 2 + 0], a.x, b.x);
            unpk(val[(s + 1) * 2 + 0], a.y, b.y);
            unpk(val[(s + 2) * 2 + 0], a.z, b.z);
            unpk(val[(s + 3) * 2 + 0], a.w, b.w);
            *(float4*)(yr0 + off) = a;
            *(float4*)(yr1 + off) = b;
        }
        cfence();
        {
            float4 c, d;
            unpk(val[(s + 0) * 2 + 1], c.x, d.x);
            unpk(val[(s + 1) * 2 + 1], c.y, d.y);
            unpk(val[(s + 2) * 2 + 1], c.z, d.z);
            unpk(val[(s + 3) * 2 + 1], c.w, d.w);
            *(float4*)(yr2 + off) = c;
            *(float4*)(yr3 + off) = d;
        }
        cfence();
    }
}

extern "C" void kernel_launch(void* const* d_in, const int* in_sizes, int n_in,
                              void* d_out, int out_size) {
    const float* X     = (const float*)d_in[0];
    const float* bp    = (const float*)d_in[1];
    const float* bias  = (const float*)d_in[2];
    const float* slope = (const float*)d_in[3];
    const float* scale = (const float*)d_in[4];
    float* Y = (float*)d_out;

    prep_all<<<(BT_ELEMS + T0_ELEMS + QT_ELEMS + 255) / 256, 256>>>(bp, bias, slope, scale);
    // 3 warps/CTA (12 rows), 3 CTAs/SM -> 9 warps/SM @ <=227 regs
    int nwarps = BATCH / 4;                 // 16384 row-groups
    int nctas = (nwarps + 2) / 3;           // 5462 (last CTA partially idle)
    net_kernel<<<nctas, 96>>>(X, Y);
}

// round 16
// speedup vs baseline: 2.5878x; 2.5878x over previous
#include <cuda_runtime.h>
#include <cstdint>

#define WIDTH  1024
#define HALF   512
#define DEPTH  8
#define BDEPTH 10
#define BATCH  65536

typedef unsigned long long ull;

// ============================ Geometry (R16) ============================
// lane = (lp<<1) | r0 : r0 = row bit, lp = p bits [5:2] (4 position bits)
// slot v (0..63): p = ((v>>2)<<6) | (lp<<2) | (v&3)  -> v bits = p {1,0,9,8,7,6}
// thread f32x2 = (row r0, row r0+2) of its 4-row group: val[v], 64 ull.
// Steps (bit b = 9-t): t=0..3 reg (v bits 5,4,3,2); t=4..7 lane (lane bits 4..1);
//                      t=8,9 reg (v bits 1,0).
// Only 4 lane steps/layer (vs 5): shfl wavefronts 640 -> 512 per layer.
//
// g_bt, per step a 1024-float4 region (reg steps use first 512):
//   reg step : [e*32 + lane], e=0..15: (c[pi=2e], s[2e], c[2e+1], s[2e+1])
//   lane step: [e*32 + lane], e=0..31: (c[v=2e],  s[2e], c[2e+1], s[2e+1])
//     (entries duplicated across the 2 row lanes + 2 pair lanes; L1 sector-merges)
// g_t0 (t=0, prev-layer quintic scale folded): [L*1024 + pi*32 + lane] = (a,b,-g,d)
//   n0 = a*x0 + b*x1 ; n1 = (-g)*x0 + d*x1, a=c*sc0, b=s*sc1, g=s*sc0, d=c*sc1.
__device__ float4 g_bt[DEPTH * BDEPTH * 1024];
__device__ float4 g_t0[DEPTH * 1024];
// quintic (scale folded out): [act*1024 + e*32 + lane] = (m[2e], nb[2e], m[2e+1], nb[2e+1])
__device__ float4 g_qt[(DEPTH - 1) * 1024];

// ---------- f32x2 helpers ----------
__device__ __forceinline__ ull pk(float lo, float hi) {
    ull r;
    asm("mov.b64 %0, {%1, %2};" : "=l"(r) : "r"(__float_as_uint(lo)), "r"(__float_as_uint(hi)));
    return r;
}
__device__ __forceinline__ void unpk(ull v, float& lo, float& hi) {
    unsigned a, b;
    asm("mov.b64 {%0, %1}, %2;" : "=r"(a), "=r"(b) : "l"(v));
    lo = __uint_as_float(a);
    hi = __uint_as_float(b);
}
__device__ __forceinline__ ull f2mul(ull a, ull b) {
    ull r;
    asm("mul.rn.f32x2 %0, %1, %2;" : "=l"(r) : "l"(a), "l"(b));
    return r;
}
__device__ __forceinline__ ull f2fma(ull a, ull b, ull c) {
    ull r;
    asm("fma.rn.f32x2 %0, %1, %2, %3;" : "=l"(r) : "l"(a), "l"(b), "l"(c));
    return r;
}
__device__ __forceinline__ void cfence() { asm volatile("" ::: "memory"); }

// ---------- prep ----------
#define BT_ELEMS (DEPTH * BDEPTH * 1024)
#define T0_ELEMS (DEPTH * 1024)
#define QT_ELEMS ((DEPTH - 1) * 1024)

__device__ __forceinline__ int bitpos(int v, int lp) {
    return ((v >> 2) << 6) | (lp << 2) | (v & 3);
}

__device__ __forceinline__ float theta_of(const float* bp, int layer, int t, int p0) {
    int j = 0;
#pragma unroll
    for (int k = 0; k < 9; k++) {
        int src = ((k - t) % 10 + 10) % 10;
        j |= ((p0 >> src) & 1) << k;
    }
    return bp[layer * (HALF * BDEPTH) + j * BDEPTH + t];
}

__global__ void prep_all(const float* __restrict__ bp,
                         const float* __restrict__ bias,
                         const float* __restrict__ slope,
                         const float* __restrict__ scale) {
    int e0 = blockIdx.x * blockDim.x + threadIdx.x;
    if (e0 < BT_ELEMS) {
        int T = e0 >> 10;
        int idx = e0 & 1023;
        int layer = T / BDEPTH;
        int t = T % BDEPTH;
        if (t == 0) return;  // handled via g_t0

        if (t <= 3 || t >= 8) {
            // reg step: first 512 entries, 2 pairs per float4
            if (idx >= 512) return;
            int e = idx >> 5;
            int lane = idx & 31;
            int lp = lane >> 1;
            int M = (t == 1) ? 16 : (t == 2) ? 8 : (t == 3) ? 4 : (t == 8) ? 2 : 1;
            float cs[4];
#pragma unroll
            for (int k = 0; k < 2; k++) {
                int pi = 2 * e + k;
                int v0 = (pi & (M - 1)) | ((pi & ~(M - 1)) << 1);
                int p0 = bitpos(v0, lp);
                float th = theta_of(bp, layer, t, p0);
                float s, c;
                sincosf(th, &s, &c);
                cs[2 * k] = c;
                cs[2 * k + 1] = s;
            }
            g_bt[e0] = make_float4(cs[0], cs[1], cs[2], cs[3]);
        } else {
            // lane step t=4..7: LM = 16 >> (t-4); pair-bit cleared for p0
            int LM = 16 >> (t - 4);
            int e = idx >> 5;          // 0..31, covers slots 2e, 2e+1
            int lane = idx & 31;
            int lp0 = (lane & ~LM) >> 1;
            float cs[4];
#pragma unroll
            for (int k = 0; k < 2; k++) {
                int v = 2 * e + k;
                int p0 = bitpos(v, lp0);
                float th = theta_of(bp, layer, t, p0);
                float s, c;
                sincosf(th, &s, &c);
                cs[2 * k] = c;
                cs[2 * k + 1] = s;
            }
            g_bt[e0] = make_float4(cs[0], cs[1], cs[2], cs[3]);
        }
    } else if (e0 < BT_ELEMS + T0_ELEMS) {
        int q = e0 - BT_ELEMS;
        int layer = q >> 10;
        int idx = q & 1023;
        int pi = idx >> 5;            // 0..31: v0 = pi, v1 = pi|32 (M=32)
        int lane = idx & 31;
        int lp = lane >> 1;
        int v0 = pi, v1 = pi | 32;
        int p0 = bitpos(v0, lp);
        int p1 = bitpos(v1, lp);
        float th = theta_of(bp, layer, 0, p0);
        float s, c;
        sincosf(th, &s, &c);
        float sc0 = 1.0f, sc1 = 1.0f;
        if (layer > 0) {
            sc0 = scale[(layer - 1) * WIDTH + p0];
            sc1 = scale[(layer - 1) * WIDTH + p1];
        }
        g_t0[q] = make_float4(c * sc0, s * sc1, -s * sc0, c * sc1);
    } else if (e0 < BT_ELEMS + T0_ELEMS + QT_ELEMS) {
        int q = e0 - BT_ELEMS - T0_ELEMS;
        int act = q >> 10;
        int idx = q & 1023;
        int e = idx >> 5;             // 0..31: slots 2e, 2e+1
        int lane = idx & 31;
        int lp = lane >> 1;
        float mv[2], nbv[2];
#pragma unroll
        for (int k = 0; k < 2; k++) {
            int v = 2 * e + k;
            int p0 = bitpos(v, lp);
            float bi = bias[act * WIDTH + p0];
            float sl = slope[act * WIDTH + p0];
            float sc = scale[act * WIDTH + p0];
            mv[k] = sl / sc;
            nbv[k] = -bi / sc;
        }
        g_qt[q] = make_float4(mv[0], nbv[0], mv[1], nbv[1]);
    }
}

// ---------- main kernel ----------

// t=0 with folded scale (M=32): n0 = a*x0 + b*x1 ; n1 = g*x0 + d*x1 (g pre-negated)
__device__ __forceinline__ void t0_step(ull (&val)[64], int lane, const float4* __restrict__ t0t) {
#pragma unroll
    for (int pi = 0; pi < 32; pi++) {
        float4 q = __ldg(t0t + pi * 32 + lane);
        ull a2 = pk(q.x, q.x);
        ull b2 = pk(q.y, q.y);
        ull g2 = pk(q.z, q.z);
        ull d2 = pk(q.w, q.w);
        const int v0 = pi, v1 = pi | 32;
        ull x0 = val[v0];
        ull x1 = val[v1];
        val[v0] = f2fma(a2, x0, f2mul(b2, x1));
        val[v1] = f2fma(g2, x0, f2mul(d2, x1));
        if ((pi & 3) == 3) cfence();
    }
}

template <int M>
__device__ __forceinline__ void reg_step(ull (&val)[64], int lane, const float4* __restrict__ bt) {
#pragma unroll
    for (int e = 0; e < 16; e++) {
        float4 q = __ldg(bt + e * 32 + lane);
#pragma unroll
        for (int k = 0; k < 2; k++) {
            const int pi = 2 * e + k;
            const int v0 = (pi & (M - 1)) | ((pi & ~(M - 1)) << 1);
            const int v1 = v0 | M;
            float c = k ? q.z : q.x;
            float s = k ? q.w : q.y;
            ull c2 = pk(c, c);
            ull s2 = pk(s, s);
            ull ns2 = s2 ^ 0x8000000080000000ULL;
            ull x0 = val[v0];
            ull x1 = val[v1];
            val[v0] = f2fma(c2, x0, f2mul(s2, x1));   // c*x0 + s*x1
            val[v1] = f2fma(c2, x1, f2mul(ns2, x0));  // c*x1 - s*x0
        }
        if ((e & 3) == 3) cfence();
    }
}

// Lane butterfly on lane bit LM (LM in {16,8,4,2}; bit 0 is the row bit).
template <int LM>
__device__ __forceinline__ void lane_step(ull (&val)[64], int lane, const float4* __restrict__ bt) {
    const ull smask = (lane & LM) ? 0x8000000080000000ULL : 0ULL;
#pragma unroll
    for (int e = 0; e < 32; e++) {
        float4 q = __ldg(bt + e * 32 + lane);
        const int va = 2 * e;
        const int vb = 2 * e + 1;
        ull xa = val[va];
        ull xb = val[vb];
        ull pa = __shfl_xor_sync(0xffffffffu, xa, LM);
        ull pb = __shfl_xor_sync(0xffffffffu, xb, LM);
        ull ca = pk(q.x, q.x);
        ull sa = pk(q.y, q.y) ^ smask;
        ull cb = pk(q.z, q.z);
        ull sb = pk(q.w, q.w) ^ smask;
        val[va] = f2fma(ca, xa, f2mul(sa, pa));
        val[vb] = f2fma(cb, xb, f2mul(sb, pb));
        if ((e & 3) == 3) cfence();
    }
}

// quintic WITHOUT trailing scale (folded into next layer's t0)
__device__ __forceinline__ void quintic(ull (&val)[64], int lane, int act) {
    const float4* __restrict__ qt = g_qt + act * 1024;
    const ull C1875 = 0x3FF000003FF00000ULL;  // (1.875, 1.875)
    const ull CM125 = 0xBFA00000BFA00000ULL;  // (-1.25, -1.25)
    const ull C0375 = 0x3EC000003EC00000ULL;  // (0.375, 0.375)
#pragma unroll
    for (int e = 0; e < 32; e++) {
        float4 q = __ldg(qt + e * 32 + lane);
#pragma unroll
        for (int k = 0; k < 2; k++) {
            const int v = 2 * e + k;
            ull m2 = pk(k ? q.z : q.x, k ? q.z : q.x);
            ull nb2 = pk(k ? q.w : q.y, k ? q.w : q.y);
            ull u = f2fma(val[v], m2, nb2);
            float lo, hi;
            unpk(u, lo, hi);
            lo = fminf(fmaxf(lo, -1.0f), 1.0f);
            hi = fminf(fmaxf(hi, -1.0f), 1.0f);
            u = pk(lo, hi);
            ull u2 = f2mul(u, u);
            ull p = f2fma(u2, C0375, CM125);
            p = f2fma(u2, p, C1875);
            val[v] = f2mul(u, p);
        }
        if ((e & 3) == 3) cfence();
    }
}

__global__ void __launch_bounds__(128)
net_kernel(const float* __restrict__ X, float* __restrict__ Y) {
    const int lane = threadIdx.x & 31;
    const int r0 = lane & 1;        // row bit (lane bit 0)
    const int lp = lane >> 1;       // 4 position bits (p[5:2])
    const int w = blockIdx.x * 4 + (threadIdx.x >> 5);
    const long long row0 = (long long)w * 4;
    // thread's two rows: r0 and r0+2
    const float* __restrict__ xrA = X + (row0 + r0) * WIDTH;
    const float* __restrict__ xrB = X + (row0 + r0 + 2) * WIDTH;

    ull val[64];

    // load: val[vhi*4 + j] = (rowA[p], rowB[p]) with p = vhi*64 + lp*4 + j
#pragma unroll
    for (int vhi = 0; vhi < 16; vhi++) {
        int off = vhi * 64 + lp * 4;
        float4 a = *(const float4*)(xrA + off);
        float4 b = *(const float4*)(xrB + off);
        int s = vhi * 4;
        val[s + 0] = pk(a.x, b.x);
        val[s + 1] = pk(a.y, b.y);
        val[s + 2] = pk(a.z, b.z);
        val[s + 3] = pk(a.w, b.w);
        if (vhi & 1) cfence();
    }

#pragma unroll 1
    for (int layer = 0; layer < DEPTH; layer++) {
        const float4* __restrict__ bt = g_bt + layer * (BDEPTH * 1024);
        t0_step(val, lane, g_t0 + layer * 1024);   // t=0: p bit 9 (v bit 5), scale-folded
        reg_step<16>(val, lane, bt + 1 * 1024);    // t=1: p bit 8 (v bit 4)
        reg_step<8>(val, lane, bt + 2 * 1024);     // t=2: p bit 7 (v bit 3)
        reg_step<4>(val, lane, bt + 3 * 1024);     // t=3: p bit 6 (v bit 2)
        lane_step<16>(val, lane, bt + 4 * 1024);   // t=4: p bit 5 (lane bit 4)
        lane_step<8>(val, lane, bt + 5 * 1024);    // t=5: p bit 4 (lane bit 3)
        lane_step<4>(val, lane, bt + 6 * 1024);    // t=6: p bit 3 (lane bit 2)
        lane_step<2>(val, lane, bt + 7 * 1024);    // t=7: p bit 2 (lane bit 1)
        reg_step<2>(val, lane, bt + 8 * 1024);     // t=8: p bit 1 (v bit 1)
        reg_step<1>(val, lane, bt + 9 * 1024);     // t=9: p bit 0 (v bit 0)
        if (layer < DEPTH - 1) quintic(val, lane, layer);
    }

    // store (all steps in-place; net permutation identity)
    float* __restrict__ yrA = Y + (row0 + r0) * WIDTH;
    float* __restrict__ yrB = Y + (row0 + r0 + 2) * WIDTH;
#pragma unroll
    for (int vhi = 0; vhi < 16; vhi++) {
        int off = vhi * 64 + lp * 4;
        int s = vhi * 4;
        float4 a, b;
        unpk(val[s + 0], a.x, b.x);
        unpk(val[s + 1], a.y, b.y);
        unpk(val[s + 2], a.z, b.z);
        unpk(val[s + 3], a.w, b.w);
        *(float4*)(yrA + off) = a;
        *(float4*)(yrB + off) = b;
        if (vhi & 1) cfence();
    }
}

extern "C" void kernel_launch(void* const* d_in, const int* in_sizes, int n_in,
                              void* d_out, int out_size) {
    const float* X     = (const float*)d_in[0];
    const float* bp    = (const float*)d_in[1];
    const float* bias  = (const float*)d_in[2];
    const float* slope = (const float*)d_in[3];
    const float* scale = (const float*)d_in[4];
    float* Y = (float*)d_out;

    prep_all<<<(BT_ELEMS + T0_ELEMS + QT_ELEMS + 255) / 256, 256>>>(bp, bias, slope, scale);
    // 4 rows/warp, 4 warps/CTA -> 16 rows/CTA; ~252 regs, 2 CTAs/SM (8 warps)
    net_kernel<<<BATCH / 16, 128>>>(X, Y);
}

// round 17
// speedup vs baseline: 3.7812x; 1.4611x over previous
#include <cuda_runtime.h>
#include <cstdint>

#define WIDTH  1024
#define HALF   512
#define DEPTH  8
#define BDEPTH 10
#define BATCH  65536

typedef unsigned long long ull;

// ============================ Geometry (R17) ============================
// Two orientations, swapped by a warp-private smem transpose (NO shuffles):
//   A: lane = p[4:0], v = p[9:5]   (layer steps t=0..4: bits 9..5 = v bits 4..0)
//   B: lane = p[9:5], v = p[4:0]   (steps t=5..9: bits 4..0 = v bits 4..0)
// val[v*2+h]: h=0 rows(0,1), h=1 rows(2,3), f32x2-packed. ALL butterflies are
// register-local; the two per-layer transposes replace 640 shfl.32/layer.
//
// g_bt (t=1..9): 256 float4/step: [e*32+lane], e=0..7 -> (c[2e],s[2e],c[2e+1],s[2e+1])
// g_t0 (t=0, A, M=16, prev-layer quintic scale folded): [L*512 + pi*32 + lane]
//   = (a,b,-g,d): n0 = a*x0 + b*x1 ; n1 = (-g)*x0 + d*x1
// g_qt (quintic in B, scale folded out): [act*512 + e*32+lane] = (m0,nb0,m1,nb1)
__device__ float4 g_bt[DEPTH * BDEPTH * 256];
__device__ float4 g_t0[DEPTH * 512];
__device__ float4 g_qt[(DEPTH - 1) * 512];

// ---------- f32x2 helpers ----------
__device__ __forceinline__ ull pk(float lo, float hi) {
    ull r;
    asm("mov.b64 %0, {%1, %2};" : "=l"(r) : "r"(__float_as_uint(lo)), "r"(__float_as_uint(hi)));
    return r;
}
__device__ __forceinline__ void unpk(ull v, float& lo, float& hi) {
    unsigned a, b;
    asm("mov.b64 {%0, %1}, %2;" : "=r"(a), "=r"(b) : "l"(v));
    lo = __uint_as_float(a);
    hi = __uint_as_float(b);
}
__device__ __forceinline__ ull f2mul(ull a, ull b) {
    ull r;
    asm("mul.rn.f32x2 %0, %1, %2;" : "=l"(r) : "l"(a), "l"(b));
    return r;
}
__device__ __forceinline__ ull f2fma(ull a, ull b, ull c) {
    ull r;
    asm("fma.rn.f32x2 %0, %1, %2, %3;" : "=l"(r) : "l"(a), "l"(b), "l"(c));
    return r;
}
__device__ __forceinline__ void cfence() { asm volatile("" ::: "memory"); }

// ---------- prep ----------
#define BT_ELEMS (DEPTH * BDEPTH * 256)
#define T0_ELEMS (DEPTH * 512)
#define QT_ELEMS ((DEPTH - 1) * 512)

__device__ __forceinline__ float theta_of(const float* bp, int layer, int t, int p0) {
    int j = 0;
#pragma unroll
    for (int k = 0; k < 9; k++) {
        int src = ((k - t) % 10 + 10) % 10;
        j |= ((p0 >> src) & 1) << k;
    }
    return bp[layer * (HALF * BDEPTH) + j * BDEPTH + t];
}

__global__ void prep_all(const float* __restrict__ bp,
                         const float* __restrict__ bias,
                         const float* __restrict__ slope,
                         const float* __restrict__ scale) {
    int e0 = blockIdx.x * blockDim.x + threadIdx.x;
    if (e0 < BT_ELEMS) {
        int T = e0 >> 8;
        int idx = e0 & 255;
        int layer = T / BDEPTH;
        int t = T % BDEPTH;
        if (t == 0) return;  // handled via g_t0
        int e = idx >> 5;
        int lane = idx & 31;
        // A steps t=1..4: v bit = 4-t ; B steps t=5..9: v bit = 9-t
        int M = (t <= 4) ? (1 << (4 - t)) : (1 << (9 - t));
        float cs[4];
#pragma unroll
        for (int k = 0; k < 2; k++) {
            int pi = 2 * e + k;
            int v0 = (pi & (M - 1)) | ((pi & ~(M - 1)) << 1);
            int p0 = (t <= 4) ? ((v0 << 5) | lane)   // A: p = v*32 + lane
                              : ((lane << 5) | v0);  // B: p = lane*32 + v
            float th = theta_of(bp, layer, t, p0);
            float s, c;
            sincosf(th, &s, &c);
            cs[2 * k] = c;
            cs[2 * k + 1] = s;
        }
        g_bt[e0] = make_float4(cs[0], cs[1], cs[2], cs[3]);
    } else if (e0 < BT_ELEMS + T0_ELEMS) {
        int q = e0 - BT_ELEMS;
        int layer = q >> 9;
        int idx = q & 511;
        int pi = idx >> 5;          // pair 0..15: v0 = pi, v1 = pi|16 (A, M=16)
        int lane = idx & 31;
        int p0 = (pi << 5) | lane;
        int p1 = ((pi | 16) << 5) | lane;
        float th = theta_of(bp, layer, 0, p0);
        float s, c;
        sincosf(th, &s, &c);
        float sc0 = 1.0f, sc1 = 1.0f;
        if (layer > 0) {
            sc0 = scale[(layer - 1) * WIDTH + p0];
            sc1 = scale[(layer - 1) * WIDTH + p1];
        }
        g_t0[q] = make_float4(c * sc0, s * sc1, -s * sc0, c * sc1);
    } else if (e0 < BT_ELEMS + T0_ELEMS + QT_ELEMS) {
        int q = e0 - BT_ELEMS - T0_ELEMS;
        int act = q >> 9;
        int idx = q & 511;
        int e = idx >> 5;           // slots v0 = 2e, v1 = 2e+1 (B orientation)
        int lane = idx & 31;
        float mv[2], nbv[2];
#pragma unroll
        for (int k = 0; k < 2; k++) {
            int v = 2 * e + k;
            int p0 = (lane << 5) | v;   // B: p = lane*32 + v
            float bi = bias[act * WIDTH + p0];
            float sl = slope[act * WIDTH + p0];
            float sc = scale[act * WIDTH + p0];
            mv[k] = sl / sc;
            nbv[k] = -bi / sc;
        }
        g_qt[q] = make_float4(mv[0], nbv[0], mv[1], nbv[1]);
    }
}

// ---------- main kernel ----------

// t=0 in A with folded scale (M=16): n0 = a*x0 + b*x1 ; n1 = g*x0 + d*x1 (g pre-negated)
__device__ __forceinline__ void t0_step(ull (&val)[64], int lane, const float4* __restrict__ t0t) {
#pragma unroll
    for (int pi = 0; pi < 16; pi++) {
        float4 q = __ldg(t0t + pi * 32 + lane);
        ull a2 = pk(q.x, q.x);
        ull b2 = pk(q.y, q.y);
        ull g2 = pk(q.z, q.z);
        ull d2 = pk(q.w, q.w);
        const int v0 = pi, v1 = pi | 16;
#pragma unroll
        for (int h = 0; h < 2; h++) {
            ull x0 = val[v0 * 2 + h];
            ull x1 = val[v1 * 2 + h];
            val[v0 * 2 + h] = f2fma(a2, x0, f2mul(b2, x1));
            val[v1 * 2 + h] = f2fma(g2, x0, f2mul(d2, x1));
        }
        if ((pi & 3) == 3) cfence();
    }
}

template <int M>
__device__ __forceinline__ void reg_step(ull (&val)[64], int lane, const float4* __restrict__ bt) {
#pragma unroll
    for (int e = 0; e < 8; e++) {
        float4 q = __ldg(bt + e * 32 + lane);
#pragma unroll
        for (int k = 0; k < 2; k++) {
            const int pi = 2 * e + k;
            const int v0 = (pi & (M - 1)) | ((pi & ~(M - 1)) << 1);
            const int v1 = v0 | M;
            float c = k ? q.z : q.x;
            float s = k ? q.w : q.y;
            ull c2 = pk(c, c);
            ull s2 = pk(s, s);
            ull ns2 = s2 ^ 0x8000000080000000ULL;
#pragma unroll
            for (int h = 0; h < 2; h++) {
                ull x0 = val[v0 * 2 + h];
                ull x1 = val[v1 * 2 + h];
                val[v0 * 2 + h] = f2fma(c2, x0, f2mul(s2, x1));   // c*x0 + s*x1
                val[v1 * 2 + h] = f2fma(c2, x1, f2mul(ns2, x0));  // c*x1 - s*x0
            }
        }
        if ((e & 3) == 3) cfence();
    }
}

// Warp-private smem transpose: swaps slot index v (5b) with lane index (5b).
// XOR-swizzled addressing -> conflict-free per half-warp for both STS and LDS.
// Buffer reused across h with __syncwarp separation. Involution (A<->B).
__device__ __forceinline__ void transpose(ull (&val)[64], int lane, ull* __restrict__ buf) {
#pragma unroll
    for (int h = 0; h < 2; h++) {
        __syncwarp();
#pragma unroll
        for (int v = 0; v < 32; v++)
            buf[lane * 32 + (v ^ lane)] = val[v * 2 + h];
        __syncwarp();
#pragma unroll
        for (int v = 0; v < 32; v++)
            val[v * 2 + h] = buf[v * 32 + (lane ^ v)];
    }
}

// quintic in B, WITHOUT trailing scale (folded into next layer's t0)
__device__ __forceinline__ void quintic(ull (&val)[64], int lane, int act) {
    const float4* __restrict__ qt = g_qt + act * 512;
    const ull C1875 = 0x3FF000003FF00000ULL;  // (1.875, 1.875)
    const ull CM125 = 0xBFA00000BFA00000ULL;  // (-1.25, -1.25)
    const ull C0375 = 0x3EC000003EC00000ULL;  // (0.375, 0.375)
#pragma unroll
    for (int e = 0; e < 16; e++) {
        float4 q = __ldg(qt + e * 32 + lane);
#pragma unroll
        for (int k = 0; k < 2; k++) {
            const int v = 2 * e + k;
            ull m2 = pk(k ? q.z : q.x, k ? q.z : q.x);
            ull nb2 = pk(k ? q.w : q.y, k ? q.w : q.y);
#pragma unroll
            for (int h = 0; h < 2; h++) {
                ull u = f2fma(val[v * 2 + h], m2, nb2);
                float lo, hi;
                unpk(u, lo, hi);
                lo = fminf(fmaxf(lo, -1.0f), 1.0f);
                hi = fminf(fmaxf(hi, -1.0f), 1.0f);
                u = pk(lo, hi);
                ull u2 = f2mul(u, u);
                ull p = f2fma(u2, C0375, CM125);
                p = f2fma(u2, p, C1875);
                val[v * 2 + h] = f2mul(u, p);
            }
        }
        if ((e & 3) == 3) cfence();
    }
}

__global__ void __launch_bounds__(128)
net_kernel(const float* __restrict__ X, float* __restrict__ Y) {
    __shared__ ull tbuf[4][1024];   // 8KB per warp, 32KB per CTA
    const int lane = threadIdx.x & 31;
    const int wic = threadIdx.x >> 5;
    ull* __restrict__ buf = tbuf[wic];
    const int w = blockIdx.x * 4 + wic;
    const long long row0 = (long long)w * 4;
    const float* __restrict__ xr0 = X + row0 * WIDTH;
    const float* __restrict__ xr1 = xr0 + WIDTH;
    const float* __restrict__ xr2 = xr1 + WIDTH;
    const float* __restrict__ xr3 = xr2 + WIDTH;

    ull val[64];

    // load in orientation A: p = v*32 + lane (LDG.32, 128B coalesced per instr)
#pragma unroll
    for (int v = 0; v < 32; v++) {
        int p = v * 32 + lane;
        val[v * 2 + 0] = pk(__ldg(xr0 + p), __ldg(xr1 + p));
        val[v * 2 + 1] = pk(__ldg(xr2 + p), __ldg(xr3 + p));
        if ((v & 3) == 3) cfence();
    }

#pragma unroll 1
    for (int layer = 0; layer < DEPTH; layer++) {
        const float4* __restrict__ bt = g_bt + layer * (BDEPTH * 256);
        // orientation A: bits 9..5 (v bits 4..0)
        t0_step(val, lane, g_t0 + layer * 512);  // t=0: bit 9 (M=16), scale-folded
        reg_step<8>(val, lane, bt + 1 * 256);    // t=1: bit 8
        reg_step<4>(val, lane, bt + 2 * 256);    // t=2: bit 7
        reg_step<2>(val, lane, bt + 3 * 256);    // t=3: bit 6
        reg_step<1>(val, lane, bt + 4 * 256);    // t=4: bit 5
        transpose(val, lane, buf);               // A -> B
        // orientation B: bits 4..0 (v bits 4..0)
        reg_step<16>(val, lane, bt + 5 * 256);   // t=5: bit 4
        reg_step<8>(val, lane, bt + 6 * 256);    // t=6: bit 3
        reg_step<4>(val, lane, bt + 7 * 256);    // t=7: bit 2
        reg_step<2>(val, lane, bt + 8 * 256);    // t=8: bit 1
        reg_step<1>(val, lane, bt + 9 * 256);    // t=9: bit 0
        if (layer < DEPTH - 1) quintic(val, lane, layer);
        transpose(val, lane, buf);               // B -> A (next layer / store)
    }

    // store in orientation A
    float* __restrict__ yr0 = Y + row0 * WIDTH;
    float* __restrict__ yr1 = yr0 + WIDTH;
    float* __restrict__ yr2 = yr1 + WIDTH;
    float* __restrict__ yr3 = yr2 + WIDTH;
#pragma unroll
    for (int v = 0; v < 32; v++) {
        int p = v * 32 + lane;
        float a, b, c, d;
        unpk(val[v * 2 + 0], a, b);
        unpk(val[v * 2 + 1], c, d);
        yr0[p] = a;
        yr1[p] = b;
        yr2[p] = c;
        yr3[p] = d;
        if ((v & 3) == 3) cfence();
    }
}

extern "C" void kernel_launch(void* const* d_in, const int* in_sizes, int n_in,
                              void* d_out, int out_size) {
    const float* X     = (const float*)d_in[0];
    const float* bp    = (const float*)d_in[1];
    const float* bias  = (const float*)d_in[2];
    const float* slope = (const float*)d_in[3];
    const float* scale = (const float*)d_in[4];
    float* Y = (float*)d_out;

    prep_all<<<(BT_ELEMS + T0_ELEMS + QT_ELEMS + 255) / 256, 256>>>(bp, bias, slope, scale);
    // 4 rows/warp, 4 warps/CTA -> 16 rows/CTA; ~252 regs, 2 CTAs/SM (8 warps)
    net_kernel<<<BATCH / 16, 128>>>(X, Y);
}